// round 2
// baseline (speedup 1.0000x reference)
#include <cuda_runtime.h>

// YOLOv1 loss, S=14, B=2, C=20, BATCH=4096.
// pred:   (4096, 14, 14, 30) fp32
// target: (4096, 14, 14, 30) fp32
// out:    scalar fp32
//
// Strategy: HBM-streaming reduction. Each block stages 128 cells (30 KB
// pred + 30 KB target) into shared via float4 streaming loads, computes the
// per-cell loss, reduces, and atomically accumulates into a double.

constexpr int NCH     = 30;   // 5*B + C
constexpr int NB      = 2;    // boxes per cell
constexpr int CPB     = 128;  // cells per block
constexpr int THREADS = 128;
constexpr int F4_PER  = CPB * NCH / 4;  // 960 float4 per tensor per block

__device__ double g_acc;

__global__ void init_k() { g_acc = 0.0; }

__global__ void __launch_bounds__(THREADS) yolo_k(
    const float* __restrict__ pred, const float* __restrict__ targ)
{
    __shared__ float4 sp4[F4_PER];
    __shared__ float4 st4[F4_PER];
    const int tid = threadIdx.x;
    const size_t base = (size_t)blockIdx.x * (CPB * NCH);
    const float4* gp = reinterpret_cast<const float4*>(pred + base);
    const float4* gt = reinterpret_cast<const float4*>(targ + base);

    // Stage: contiguous, coalesced, streaming (evict-first) loads.
    #pragma unroll
    for (int i = tid; i < F4_PER; i += THREADS) {
        sp4[i] = __ldcs(gp + i);
        st4[i] = __ldcs(gt + i);
    }
    __syncthreads();

    const float* P = reinterpret_cast<const float*>(sp4) + tid * NCH;
    const float* T = reinterpret_cast<const float*>(st4) + tid * NCH;

    const float invS = 1.0f / 14.0f;

    const float tobj = T[4];
    const float of = (tobj > 0.0f) ? 1.0f : 0.0f;
    const float nf = 1.0f - of;

    // Target box (box 0 of the tiled pair), in xyxy.
    const float tx0 = T[0] * invS - 0.5f * T[2];
    const float ty0 = T[1] * invS - 0.5f * T[3];
    const float tx1 = T[0] * invS + 0.5f * T[2];
    const float ty1 = T[1] * invS + 0.5f * T[3];
    const float area_t = (tx1 - tx0) * (ty1 - ty0);

    float iou[NB];
    #pragma unroll
    for (int b = 0; b < NB; ++b) {
        const float* Pb = P + 5 * b;
        const float px0 = Pb[0] * invS - 0.5f * Pb[2];
        const float py0 = Pb[1] * invS - 0.5f * Pb[3];
        const float px1 = Pb[0] * invS + 0.5f * Pb[2];
        const float py1 = Pb[1] * invS + 0.5f * Pb[3];
        const float ltx = fmaxf(px0, tx0), lty = fmaxf(py0, ty0);
        const float rbx = fminf(px1, tx1), rby = fminf(py1, ty1);
        const float wx = fmaxf(rbx - ltx, 0.0f);
        const float wy = fmaxf(rby - lty, 0.0f);
        const float inter = wx * wy;
        const float area_p = (px1 - px0) * (py1 - py0);
        // area_p > 0 always (pred wh in (0.001, 1)), so division is safe.
        iou[b] = inter / (area_p + area_t - inter);
    }
    // jnp.argmax takes the FIRST max -> idx=1 only on strict greater.
    const int idx = (iou[1] > iou[0]) ? 1 : 0;
    const float max_iou = fmaxf(iou[0], iou[1]);

    float lxy = 0.0f, lwh = 0.0f, lobj = 0.0f, lnoobj = 0.0f;
    #pragma unroll
    for (int b = 0; b < NB; ++b) {
        const float* Pb = P + 5 * b;
        const float* Tb = T + 5 * b;
        const bool resp = (of > 0.0f) && (idx == b);
        const float rf = resp ? 1.0f : 0.0f;

        const float dx = Pb[0] - Tb[0];
        const float dy = Pb[1] - Tb[1];
        lxy += rf * (dx * dx + dy * dy);

        const float pw = resp ? Pb[2] : 1.0f;
        const float tw = resp ? Tb[2] : 1.0f;
        const float ph = resp ? Pb[3] : 1.0f;
        const float th = resp ? Tb[3] : 1.0f;
        const float dw = sqrtf(pw) - sqrtf(tw);
        const float dh = sqrtf(ph) - sqrtf(th);
        lwh += rf * (dw * dw + dh * dh);

        const float dob = Pb[4] - max_iou;
        lobj += rf * dob * dob;

        const float dn = Pb[4] - Tb[4];
        lnoobj += dn * dn;
    }
    lnoobj *= nf;

    float lcls = 0.0f;
    #pragma unroll
    for (int k = 10; k < 30; ++k) {
        const float d = P[k] - T[k];
        lcls += d * d;
    }
    lcls *= of;

    float v = 5.0f * (lxy + lwh) + lobj + 0.5f * lnoobj + lcls;

    // Warp reduce -> block reduce -> one double atomic per block.
    #pragma unroll
    for (int o = 16; o > 0; o >>= 1)
        v += __shfl_down_sync(0xffffffffu, v, o);

    __shared__ float wsum[THREADS / 32];
    if ((tid & 31) == 0) wsum[tid >> 5] = v;
    __syncthreads();
    if (tid == 0) {
        float s = 0.0f;
        #pragma unroll
        for (int w = 0; w < THREADS / 32; ++w) s += wsum[w];
        atomicAdd(&g_acc, (double)s);
    }
}

__global__ void fin_k(float* out) {
    out[0] = (float)(g_acc * (1.0 / 4096.0));
}

extern "C" void kernel_launch(void* const* d_in, const int* in_sizes, int n_in,
                              void* d_out, int out_size)
{
    const float* pred = (const float*)d_in[0];
    const float* targ = (const float*)d_in[1];
    float* out = (float*)d_out;

    const int cells  = in_sizes[0] / NCH;       // 802816
    const int blocks = cells / CPB;             // 6272 (exact)

    init_k<<<1, 1>>>();
    yolo_k<<<blocks, THREADS>>>(pred, targ);
    fin_k<<<1, 1>>>(out);
}